// round 8
// baseline (speedup 1.0000x reference)
#include <cuda_runtime.h>
#include <cuda_bf16.h>
#include <mma.h>
#include <cstdint>

// ManeuverHead on GB300 — 2 kernels.
//  k_front: persistent fused front end (grid barriers): init + masked scans +
//           boundary cbase + scatter + w1 repack to bf16 tile-major.
//  k_main : 512 blocks x 64 slots x 256 threads (8 warps), launch_bounds(256,3).
//           bf16 WMMA layer 1 (fb fragments from tile-major GLOBAL w1, ldm 16),
//           batched-MLP gather, in-place fp32 relu+b1, tf32 WMMA layer 2.
// N=262144, B=4096, D=128, G=8, R=7.

#define NNODES   262144
#define NB       4096
#define GG       8
#define RR       7
#define NSLOTS   (NB * GG)
#define NEGV     (-1e9f)
#define FGRID    256

using namespace nvcuda;

// ---------------- device scratch ------------------------------------------
__device__ int            d_blockSums[FGRID];
__device__ int            d_blockOff[FGRID];
__device__ int            d_cbase[NB];
__device__ int            d_slotNode[NSLOTS];
__device__ __nv_bfloat16  d_w1t[32768];    // w1 [256][128] bf16, 16x16 TILE-MAJOR:
                                           // tile (kt,nt) at (kt*8+nt)*256
__device__ unsigned int   g_cnt;           // zero-init
__device__ volatile unsigned int g_gen;    // zero-init

// ---------------- K1: fused front end --------------------------------------
__global__ void __launch_bounds__(256)
k_front(const int* __restrict__ mask, const int* __restrict__ batch,
        const float* __restrict__ w1) {
    int t = threadIdx.x, bid = blockIdx.x;
    int lane = t & 31, warp = t >> 5;
    int gid = bid * 256 + t;

    __shared__ int ws[8];
    __shared__ unsigned int s_gen;
    __shared__ int s_lead;

    // ---- P0: aux init + w1 tile-major bf16 repack ----
    if (gid < NSLOTS) d_slotNode[gid] = -1;
    if (gid < 32768) {
        int kk = gid >> 7, n = gid & 127;
        int dst = ((kk >> 4) * 8 + (n >> 4)) * 256 + (kk & 15) * 16 + (n & 15);
        d_w1t[dst] = __float2bfloat16(w1[gid]);
    }

    // ---- P0: block scan of masked flags ----
    int4 m = ((const int4*)mask)[gid];
    int4 b = ((const int4*)batch)[gid];
    int g0 = m.x != 0, g1 = m.y != 0, g2 = m.z != 0, g3 = m.w != 0;
    int s = g0 + g1 + g2 + g3;
    int inc = s;
#pragma unroll
    for (int o = 1; o < 32; o <<= 1) {
        int v = __shfl_up_sync(~0u, inc, o);
        if (lane >= o) inc += v;
    }
    if (lane == 31) ws[warp] = inc;
    __syncthreads();
    if (warp == 0 && lane < 8) {
        int v = ws[lane], iv = v;
#pragma unroll
        for (int o = 1; o < 8; o <<= 1) {
            int x = __shfl_up_sync(0xffu, iv, o);
            if (lane >= o) iv += x;
        }
        ws[lane] = iv - v;
        if (lane == 7) d_blockSums[bid] = iv;
    }
    __syncthreads();
    int lexcl = ws[warp] + (inc - s);

    // ---- BAR1: leader scans blockSums -> blockOff ----
    __threadfence();
    __syncthreads();
    if (t == 0) {
        s_gen = g_gen;
        unsigned int a = atomicAdd(&g_cnt, 1u);
        s_lead = (a == (unsigned)gridDim.x - 1u);
    }
    __syncthreads();
    if (s_lead) {
        __threadfence();
        int v = d_blockSums[t];
        int iv = v;
#pragma unroll
        for (int o = 1; o < 32; o <<= 1) {
            int x = __shfl_up_sync(~0u, iv, o);
            if (lane >= o) iv += x;
        }
        if (lane == 31) ws[warp] = iv;
        __syncthreads();
        if (warp == 0 && lane < 8) {
            int v2 = ws[lane], iv2 = v2;
#pragma unroll
            for (int o = 1; o < 8; o <<= 1) {
                int x = __shfl_up_sync(0xffu, iv2, o);
                if (lane >= o) iv2 += x;
            }
            ws[lane] = iv2 - v2;
        }
        __syncthreads();
        d_blockOff[t] = ws[warp] + (iv - v);
        __threadfence();
        __syncthreads();
        if (t == 0) {
            *(volatile unsigned int*)&g_cnt = 0u;
            __threadfence();
            g_gen = s_gen + 1u;
        }
    } else {
        if (t == 0) {
            while (g_gen == s_gen) __nanosleep(64);
            __threadfence();
        }
        __syncthreads();
    }

    // ---- P2: boundary nodes write cbase ----
    int pe0 = d_blockOff[bid] + lexcl;
    int pw = __shfl_up_sync(~0u, b.w, 1);
    int prevb = (lane == 0) ? ((gid > 0) ? batch[gid * 4 - 1] : -1) : pw;
    {
        int pe = pe0;
        if (b.x != prevb) d_cbase[b.x] = pe;  pe += g0;
        if (b.y != b.x)   d_cbase[b.y] = pe;  pe += g1;
        if (b.z != b.y)   d_cbase[b.z] = pe;  pe += g2;
        if (b.w != b.z)   d_cbase[b.w] = pe;
    }

    // ---- BAR2 ----
    __threadfence();
    __syncthreads();
    if (t == 0) {
        s_gen = g_gen;
        unsigned int a = atomicAdd(&g_cnt, 1u);
        s_lead = (a == (unsigned)gridDim.x - 1u);
    }
    __syncthreads();
    if (s_lead) {
        if (t == 0) {
            *(volatile unsigned int*)&g_cnt = 0u;
            __threadfence();
            g_gen = s_gen + 1u;
        }
        __syncthreads();
    } else {
        if (t == 0) {
            while (g_gen == s_gen) __nanosleep(64);
            __threadfence();
        }
        __syncthreads();
    }

    // ---- P3: scatter ----
    int base = gid * 4;
    int pre = pe0;
    if (g0) { int r = pre - d_cbase[b.x]; if (r < GG) d_slotNode[b.x * GG + r] = base;     pre++; }
    if (g1) { int r = pre - d_cbase[b.y]; if (r < GG) d_slotNode[b.y * GG + r] = base + 1; pre++; }
    if (g2) { int r = pre - d_cbase[b.z]; if (r < GG) d_slotNode[b.z * GG + r] = base + 2; pre++; }
    if (g3) { int r = pre - d_cbase[b.w]; if (r < GG) d_slotNode[b.w * GG + r] = base + 3; }
}

// ---------------- K2: main -------------------------------------------------
// 512 blocks x 64 slots, 256 threads, 8 warps in a 2x4 grid:
//   mw = w>>2 (m-tiles {2mw,2mw+1}), nw = w&3 (n-tiles {2nw,2nw+1}).
// smem (bytes):
//   As  bf16 [64][280] @0        (35840)   A: K=256 (node|global), ldm 280
//   H32 fp32 [64][132] @0        (33792)   aliases As after layer 1
//   Sc  fp32 [64][20]  @35840    (5120)
//   W2f fp32 [128][16] @40960    (8192)
//   nodeS int [64]     @49152    (256)
//   b1s fp32 [128]     @49408    (512)
//   b2s fp32 [8]       @49920    (32)
#define OFF_SC    35840
#define OFF_W2    40960
#define OFF_NODE  49152
#define OFF_B1    49408
#define OFF_B2    49920
#define MAIN_SMEM_BYTES 49984

__global__ void __launch_bounds__(256, 3)
k_main(const float* __restrict__ nf,
       const float* __restrict__ gf,
       const float* __restrict__ b1,
       const float* __restrict__ w2,
       const float* __restrict__ b2,
       const int* __restrict__ mvm,
       float* __restrict__ out) {
    extern __shared__ __align__(16) unsigned char sm[];
    __nv_bfloat16* As   = (__nv_bfloat16*)sm;                 // ldm 280
    float*         H32  = (float*)sm;                         // ldm 132
    float*         Sc   = (float*)(sm + OFF_SC);              // ldm 20
    float*         W2f  = (float*)(sm + OFF_W2);              // ldm 16
    int*           nodeS= (int*)(sm + OFF_NODE);
    float*         b1s  = (float*)(sm + OFF_B1);
    float*         b2s  = (float*)(sm + OFF_B2);

    int t = threadIdx.x, w = t >> 5, lane = t & 31;
    int slot0 = blockIdx.x * 64;
    int b0 = blockIdx.x * 8;

    if (t < 64) nodeS[t] = d_slotNode[slot0 + t];
    for (int i = t; i < 2048; i += 256) {          // w2 padded fp32 [128][16]
        int j = i >> 4, r = i & 15;
        W2f[i] = (r < RR) ? w2[j * RR + r] : 0.f;
    }
    if (t < 128) b1s[t] = b1[t];
    if (t < RR)  b2s[t] = b2[t];
    __syncthreads();                               // nodeS ready

    // ---- gather A (batched MLP=8). Per thread: fixed col group c=t&63,
    //      rows row0 + 4*jj. c<32 -> node half; c>=32 -> global half. ----
    {
        int c = t & 63;
        int row0 = t >> 6;                         // 0..3
        const float4 z = make_float4(0.f, 0.f, 0.f, 0.f);
#pragma unroll
        for (int pass = 0; pass < 2; pass++) {
            float4 v[8];
            if (c < 32) {
                const float4* nf4 = (const float4*)nf;
#pragma unroll
                for (int j = 0; j < 8; j++) {
                    int row = row0 + (pass * 8 + j) * 4;
                    int nd = nodeS[row];
                    v[j] = (nd >= 0) ? nf4[nd * 32 + c] : z;
                }
            } else {
                const float4* gf4 = (const float4*)gf;
#pragma unroll
                for (int j = 0; j < 8; j++) {
                    int row = row0 + (pass * 8 + j) * 4;
                    v[j] = gf4[(b0 + (row >> 3)) * 32 + (c - 32)];
                }
            }
#pragma unroll
            for (int j = 0; j < 8; j++) {
                int row = row0 + (pass * 8 + j) * 4;
                __nv_bfloat162 p0 = __floats2bfloat162_rn(v[j].x, v[j].y);
                __nv_bfloat162 p1 = __floats2bfloat162_rn(v[j].z, v[j].w);
                uint2 pk;
                pk.x = *reinterpret_cast<unsigned int*>(&p0);
                pk.y = *reinterpret_cast<unsigned int*>(&p1);
                *(uint2*)(As + row * 280 + c * 4) = pk;
            }
        }
    }
    __syncthreads();

    // ---- layer 1: H(64x128) = A(64x256) @ w1(256x128) ----
    int mw = w >> 2, nw = w & 3;
    wmma::fragment<wmma::matrix_a, 16, 16, 16, __nv_bfloat16, wmma::row_major> fa[2];
    wmma::fragment<wmma::matrix_b, 16, 16, 16, __nv_bfloat16, wmma::row_major> fb;
    wmma::fragment<wmma::accumulator, 16, 16, 16, float> fc[2][2];
#pragma unroll
    for (int i = 0; i < 2; i++)
#pragma unroll
        for (int n = 0; n < 2; n++) wmma::fill_fragment(fc[i][n], 0.f);

#pragma unroll
    for (int k = 0; k < 16; k++) {
#pragma unroll
        for (int i = 0; i < 2; i++)
            wmma::load_matrix_sync(fa[i], As + (2 * mw + i) * 16 * 280 + 16 * k, 280);
#pragma unroll
        for (int n = 0; n < 2; n++) {
            int nt = 2 * nw + n;
            wmma::load_matrix_sync(fb, d_w1t + (k * 8 + nt) * 256, 16);
#pragma unroll
            for (int i = 0; i < 2; i++)
                wmma::mma_sync(fc[i][n], fa[i], fb, fc[i][n]);
        }
    }
    __syncthreads();                               // As dead -> H32 aliases it
#pragma unroll
    for (int i = 0; i < 2; i++)
#pragma unroll
        for (int n = 0; n < 2; n++)
            wmma::store_matrix_sync(H32 + (2 * mw + i) * 16 * 132 + 16 * (2 * nw + n),
                                    fc[i][n], 132, wmma::mem_row_major);
    __syncthreads();                               // full H visible

    // ---- relu(H + b1) in place, fp32: thread owns row t>>2, quarter t&3 ----
    {
        int row = t >> 2, q = t & 3;
        float4* hr = (float4*)(H32 + row * 132 + q * 32);
        const float4* br = (const float4*)(b1s + q * 32);
#pragma unroll
        for (int j = 0; j < 8; j++) {
            float4 h = hr[j], g = br[j];
            h.x = fmaxf(h.x + g.x, 0.f);
            h.y = fmaxf(h.y + g.y, 0.f);
            h.z = fmaxf(h.z + g.z, 0.f);
            h.w = fmaxf(h.w + g.w, 0.f);
            hr[j] = h;
        }
    }
    __syncthreads();

    // ---- layer 2 (tf32) on warps 0..3: Sc(16x16) = H(16x128) @ W2f ----
    if (w < 4) {
        wmma::fragment<wmma::matrix_a, 16, 16, 8, wmma::precision::tf32, wmma::row_major> fa2;
        wmma::fragment<wmma::matrix_b, 16, 16, 8, wmma::precision::tf32, wmma::row_major> fb2;
        wmma::fragment<wmma::accumulator, 16, 16, 8, float> fc2;
        wmma::fill_fragment(fc2, 0.f);
#pragma unroll
        for (int k = 0; k < 16; k++) {
            wmma::load_matrix_sync(fa2, H32 + 16 * w * 132 + 8 * k, 132);
            wmma::load_matrix_sync(fb2, W2f + 8 * k * 16, 16);
#pragma unroll
            for (int i = 0; i < fa2.num_elements; i++)
                fa2.x[i] = wmma::__float_to_tf32(fa2.x[i]);
#pragma unroll
            for (int i = 0; i < fb2.num_elements; i++)
                fb2.x[i] = wmma::__float_to_tf32(fb2.x[i]);
            wmma::mma_sync(fc2, fa2, fb2, fc2);
        }
        wmma::store_matrix_sync(Sc + 16 * w * 20, fc2, 20, wmma::mem_row_major);
    }
    __syncthreads();

    // ---- masked output: 448 outputs over 256 threads ----
    for (int idx = t; idx < 64 * RR; idx += 256) {
        int m = idx / RR, r = idx - m * RR;
        int bb = b0 + (m >> 3);
        int orow = bb * (GG * RR) + (m & 7) * RR;
        float v = NEGV;
        if (nodeS[m] >= 0 && mvm[orow + r] != 0)
            v = Sc[m * 20 + r] + b2s[r];
        out[orow + r] = v;
    }
}

// ---------------- launch ---------------------------------------------------
extern "C" void kernel_launch(void* const* d_in, const int* in_sizes, int n_in,
                              void* d_out, int out_size) {
    const float* nf    = (const float*)d_in[0];
    const float* gf    = (const float*)d_in[1];
    const int*   gmask = (const int*)d_in[2];
    const int*   mvm   = (const int*)d_in[3];
    const int*   batch = (const int*)d_in[4];
    const float* w1    = (const float*)d_in[5];
    const float* b1    = (const float*)d_in[6];
    const float* w2    = (const float*)d_in[7];
    const float* b2    = (const float*)d_in[8];
    float*       out   = (float*)d_out;

    cudaFuncSetAttribute(k_main, cudaFuncAttributeMaxDynamicSharedMemorySize,
                         MAIN_SMEM_BYTES);

    k_front<<<FGRID, 256>>>(gmask, batch, w1);
    k_main<<<512, 256, MAIN_SMEM_BYTES>>>(nf, gf, b1, w2, b2, mvm, out);
}

// round 9
// speedup vs baseline: 1.1751x; 1.1751x over previous
#include <cuda_runtime.h>
#include <cuda_bf16.h>
#include <mma.h>
#include <cstdint>

// ManeuverHead on GB300 — 2 kernels.
//  k_front: persistent fused front end (grid barriers): init + masked scans +
//           boundary cbase + scatter + w1 repack to bf16 tile-major.
//  k_main : 512 blocks x 64 slots x 128 threads (4 warps).
//           Layer 1 split: global-feature half DEDUPLICATED per batch
//           (16x128x128 mini-GEMM) + node half (64x128x128). fb fragments
//           from tile-major GLOBAL w1 (L1-resident). fp32 relu + b1 + gpart,
//           tf32 WMMA layer 2, masked output.
// N=262144, B=4096, D=128, G=8, R=7.

#define NNODES   262144
#define NB       4096
#define GG       8
#define RR       7
#define NSLOTS   (NB * GG)
#define NEGV     (-1e9f)
#define FGRID    256

using namespace nvcuda;

// ---------------- device scratch ------------------------------------------
__device__ int            d_blockSums[FGRID];
__device__ int            d_blockOff[FGRID];
__device__ int            d_cbase[NB];
__device__ int            d_slotNode[NSLOTS];
__device__ __nv_bfloat16  d_w1t[32768];    // w1 [256][128] bf16, 16x16 TILE-MAJOR:
                                           // tile (kt,nt) at (kt*8+nt)*256
__device__ unsigned int   g_cnt;           // zero-init
__device__ volatile unsigned int g_gen;    // zero-init

// ---------------- K1: fused front end --------------------------------------
__global__ void __launch_bounds__(256)
k_front(const int* __restrict__ mask, const int* __restrict__ batch,
        const float* __restrict__ w1) {
    int t = threadIdx.x, bid = blockIdx.x;
    int lane = t & 31, warp = t >> 5;
    int gid = bid * 256 + t;

    __shared__ int ws[8];
    __shared__ unsigned int s_gen;
    __shared__ int s_lead;

    // ---- P0: aux init + w1 tile-major bf16 repack ----
    if (gid < NSLOTS) d_slotNode[gid] = -1;
    if (gid < 32768) {
        int kk = gid >> 7, n = gid & 127;
        int dst = ((kk >> 4) * 8 + (n >> 4)) * 256 + (kk & 15) * 16 + (n & 15);
        d_w1t[dst] = __float2bfloat16(w1[gid]);
    }

    // ---- P0: block scan of masked flags ----
    int4 m = ((const int4*)mask)[gid];
    int4 b = ((const int4*)batch)[gid];
    int g0 = m.x != 0, g1 = m.y != 0, g2 = m.z != 0, g3 = m.w != 0;
    int s = g0 + g1 + g2 + g3;
    int inc = s;
#pragma unroll
    for (int o = 1; o < 32; o <<= 1) {
        int v = __shfl_up_sync(~0u, inc, o);
        if (lane >= o) inc += v;
    }
    if (lane == 31) ws[warp] = inc;
    __syncthreads();
    if (warp == 0 && lane < 8) {
        int v = ws[lane], iv = v;
#pragma unroll
        for (int o = 1; o < 8; o <<= 1) {
            int x = __shfl_up_sync(0xffu, iv, o);
            if (lane >= o) iv += x;
        }
        ws[lane] = iv - v;
        if (lane == 7) d_blockSums[bid] = iv;
    }
    __syncthreads();
    int lexcl = ws[warp] + (inc - s);

    // ---- BAR1: leader scans blockSums -> blockOff ----
    __threadfence();
    __syncthreads();
    if (t == 0) {
        s_gen = g_gen;
        unsigned int a = atomicAdd(&g_cnt, 1u);
        s_lead = (a == (unsigned)gridDim.x - 1u);
    }
    __syncthreads();
    if (s_lead) {
        __threadfence();
        int v = d_blockSums[t];
        int iv = v;
#pragma unroll
        for (int o = 1; o < 32; o <<= 1) {
            int x = __shfl_up_sync(~0u, iv, o);
            if (lane >= o) iv += x;
        }
        if (lane == 31) ws[warp] = iv;
        __syncthreads();
        if (warp == 0 && lane < 8) {
            int v2 = ws[lane], iv2 = v2;
#pragma unroll
            for (int o = 1; o < 8; o <<= 1) {
                int x = __shfl_up_sync(0xffu, iv2, o);
                if (lane >= o) iv2 += x;
            }
            ws[lane] = iv2 - v2;
        }
        __syncthreads();
        d_blockOff[t] = ws[warp] + (iv - v);
        __threadfence();
        __syncthreads();
        if (t == 0) {
            *(volatile unsigned int*)&g_cnt = 0u;
            __threadfence();
            g_gen = s_gen + 1u;
        }
    } else {
        if (t == 0) {
            while (g_gen == s_gen) __nanosleep(64);
            __threadfence();
        }
        __syncthreads();
    }

    // ---- P2: boundary nodes write cbase ----
    int pe0 = d_blockOff[bid] + lexcl;
    int pw = __shfl_up_sync(~0u, b.w, 1);
    int prevb = (lane == 0) ? ((gid > 0) ? batch[gid * 4 - 1] : -1) : pw;
    {
        int pe = pe0;
        if (b.x != prevb) d_cbase[b.x] = pe;  pe += g0;
        if (b.y != b.x)   d_cbase[b.y] = pe;  pe += g1;
        if (b.z != b.y)   d_cbase[b.z] = pe;  pe += g2;
        if (b.w != b.z)   d_cbase[b.w] = pe;
    }

    // ---- BAR2 ----
    __threadfence();
    __syncthreads();
    if (t == 0) {
        s_gen = g_gen;
        unsigned int a = atomicAdd(&g_cnt, 1u);
        s_lead = (a == (unsigned)gridDim.x - 1u);
    }
    __syncthreads();
    if (s_lead) {
        if (t == 0) {
            *(volatile unsigned int*)&g_cnt = 0u;
            __threadfence();
            g_gen = s_gen + 1u;
        }
        __syncthreads();
    } else {
        if (t == 0) {
            while (g_gen == s_gen) __nanosleep(64);
            __threadfence();
        }
        __syncthreads();
    }

    // ---- P3: scatter ----
    int base = gid * 4;
    int pre = pe0;
    if (g0) { int r = pre - d_cbase[b.x]; if (r < GG) d_slotNode[b.x * GG + r] = base;     pre++; }
    if (g1) { int r = pre - d_cbase[b.y]; if (r < GG) d_slotNode[b.y * GG + r] = base + 1; pre++; }
    if (g2) { int r = pre - d_cbase[b.z]; if (r < GG) d_slotNode[b.z * GG + r] = base + 2; pre++; }
    if (g3) { int r = pre - d_cbase[b.w]; if (r < GG) d_slotNode[b.w * GG + r] = base + 3; }
}

// ---------------- K2: main -------------------------------------------------
// 512 blocks x 64 slots (8 batches), 128 threads, 4 warps.
// Warp w: node GEMM over all 4 m-tiles x n-tiles {2w,2w+1} (k = 8 tiles);
//         global mini-GEMM (Ag 16x128, rows 0..7 = batch globals) same n-tiles.
// smem (bytes):
//   union @0 size 33792:
//     As bf16 [64][136] @0      (17408)    node-feature A tile
//     Ag bf16 [16][136] @17408  (4352)     per-batch global A tile (rows 8..15 = 0)
//     H32 fp32 [64][132] @0     (33792)    aliases As/Ag after layer 1
//   GP  fp32 [16][132] @33792   (8448)     gpart = Ag @ w1[128:]
//   Sc  fp32 [64][16]  @42240   (4096)
//   W2f fp32 [128][16] @46336   (8192)
//   nodeS int [64]     @54528   (256)
//   b1s fp32 [128]     @54784   (512)
//   b2s fp32 [8]       @55296   (32)
#define OFF_AG    17408
#define OFF_GP    33792
#define OFF_SC    42240
#define OFF_W2    46336
#define OFF_NODE  54528
#define OFF_B1    54784
#define OFF_B2    55296
#define MAIN_SMEM_BYTES 55328

__global__ void __launch_bounds__(128, 4)
k_main(const float* __restrict__ nf,
       const float* __restrict__ gf,
       const float* __restrict__ b1,
       const float* __restrict__ w2,
       const float* __restrict__ b2,
       const int* __restrict__ mvm,
       float* __restrict__ out) {
    extern __shared__ __align__(16) unsigned char sm[];
    __nv_bfloat16* As   = (__nv_bfloat16*)sm;                 // ldm 136
    __nv_bfloat16* Ag   = (__nv_bfloat16*)(sm + OFF_AG);      // ldm 136
    float*         H32  = (float*)sm;                         // ldm 132
    float*         GP   = (float*)(sm + OFF_GP);              // ldm 132
    float*         Sc   = (float*)(sm + OFF_SC);              // ldm 16
    float*         W2f  = (float*)(sm + OFF_W2);              // ldm 16
    int*           nodeS= (int*)(sm + OFF_NODE);
    float*         b1s  = (float*)(sm + OFF_B1);
    float*         b2s  = (float*)(sm + OFF_B2);

    int t = threadIdx.x, w = t >> 5, lane = t & 31;
    int slot0 = blockIdx.x * 64;
    int b0 = blockIdx.x * 8;

    if (t < 64) nodeS[t] = d_slotNode[slot0 + t];
    for (int i = t; i < 2048; i += 128) {          // w2 padded fp32 [128][16]
        int j = i >> 4, r = i & 15;
        W2f[i] = (r < RR) ? w2[j * RR + r] : 0.f;
    }
    if (t < 128) b1s[t] = b1[t];
    if (t < RR)  b2s[t] = b2[t];
    __syncthreads();                               // nodeS ready

    {   // stage Ag: rows 0..7 = gf[b0..b0+7], rows 8..15 = 0  (512 float4)
        const float4* gf4 = (const float4*)gf;
        const float4 z = make_float4(0.f, 0.f, 0.f, 0.f);
        for (int i = t; i < 512; i += 128) {
            int row = i >> 5, c = i & 31;
            float4 v = (row < 8) ? gf4[(b0 + row) * 32 + c] : z;
            __nv_bfloat162 p0 = __floats2bfloat162_rn(v.x, v.y);
            __nv_bfloat162 p1 = __floats2bfloat162_rn(v.z, v.w);
            uint2 pk;
            pk.x = *reinterpret_cast<unsigned int*>(&p0);
            pk.y = *reinterpret_cast<unsigned int*>(&p1);
            *(uint2*)(Ag + row * 136 + c * 4) = pk;
        }
        // gather As: node rows (zeros for empty slots) (2048 float4)
        const float4* nf4 = (const float4*)nf;
        for (int i = t; i < 2048; i += 128) {
            int row = i >> 5, c = i & 31;
            int nd = nodeS[row];
            float4 v = (nd >= 0) ? nf4[nd * 32 + c] : z;
            __nv_bfloat162 p0 = __floats2bfloat162_rn(v.x, v.y);
            __nv_bfloat162 p1 = __floats2bfloat162_rn(v.z, v.w);
            uint2 pk;
            pk.x = *reinterpret_cast<unsigned int*>(&p0);
            pk.y = *reinterpret_cast<unsigned int*>(&p1);
            *(uint2*)(As + row * 136 + c * 4) = pk;
        }
    }
    __syncthreads();

    // ---- global mini-GEMM first (frees gc regs before node GEMM) ----
    // GP(16x128) = Ag(16x128) @ w1[128:256]  (kt = 8..15 in tile-major w1)
    {
        wmma::fragment<wmma::matrix_a, 16, 16, 16, __nv_bfloat16, wmma::row_major> ga;
        wmma::fragment<wmma::matrix_b, 16, 16, 16, __nv_bfloat16, wmma::row_major> gb;
        wmma::fragment<wmma::accumulator, 16, 16, 16, float> gc[2];
#pragma unroll
        for (int n = 0; n < 2; n++) wmma::fill_fragment(gc[n], 0.f);
#pragma unroll
        for (int k = 0; k < 8; k++) {
            wmma::load_matrix_sync(ga, Ag + 16 * k, 136);
#pragma unroll
            for (int n = 0; n < 2; n++) {
                int nt = 2 * w + n;
                wmma::load_matrix_sync(gb, d_w1t + ((8 + k) * 8 + nt) * 256, 16);
                wmma::mma_sync(gc[n], ga, gb, gc[n]);
            }
        }
#pragma unroll
        for (int n = 0; n < 2; n++)
            wmma::store_matrix_sync(GP + 16 * (2 * w + n), gc[n], 132,
                                    wmma::mem_row_major);
    }

    // ---- node GEMM: Hn(64x128) = As(64x128) @ w1[0:128] ----
    wmma::fragment<wmma::matrix_a, 16, 16, 16, __nv_bfloat16, wmma::row_major> fa;
    wmma::fragment<wmma::matrix_b, 16, 16, 16, __nv_bfloat16, wmma::row_major> fb;
    wmma::fragment<wmma::accumulator, 16, 16, 16, float> fc[4][2];
#pragma unroll
    for (int mt = 0; mt < 4; mt++)
#pragma unroll
        for (int n = 0; n < 2; n++) wmma::fill_fragment(fc[mt][n], 0.f);

#pragma unroll
    for (int k = 0; k < 8; k++) {
#pragma unroll
        for (int n = 0; n < 2; n++) {
            int nt = 2 * w + n;
            wmma::load_matrix_sync(fb, d_w1t + (k * 8 + nt) * 256, 16);
#pragma unroll
            for (int mt = 0; mt < 4; mt++) {
                wmma::load_matrix_sync(fa, As + mt * 16 * 136 + 16 * k, 136);
                wmma::mma_sync(fc[mt][n], fa, fb, fc[mt][n]);
            }
        }
    }
    __syncthreads();                               // As/Ag dead -> H32 aliases
#pragma unroll
    for (int mt = 0; mt < 4; mt++)
#pragma unroll
        for (int n = 0; n < 2; n++)
            wmma::store_matrix_sync(H32 + mt * 16 * 132 + 16 * (2 * w + n),
                                    fc[mt][n], 132, wmma::mem_row_major);
    __syncthreads();                               // full H + GP visible

    // ---- relu(H + b1 + GP[batch]) in place, fp32 ----
    {
        int row = t >> 1, half = t & 1;            // row 0..63, half 0..1
        float4* hr = (float4*)(H32 + row * 132 + half * 64);
        const float4* br = (const float4*)(b1s + half * 64);
        const float4* gr = (const float4*)(GP + (row >> 3) * 132 + half * 64);
#pragma unroll
        for (int j = 0; j < 16; j++) {
            float4 h = hr[j], g = br[j], p = gr[j];
            h.x = fmaxf(h.x + g.x + p.x, 0.f);
            h.y = fmaxf(h.y + g.y + p.y, 0.f);
            h.z = fmaxf(h.z + g.z + p.z, 0.f);
            h.w = fmaxf(h.w + g.w + p.w, 0.f);
            hr[j] = h;
        }
    }
    __syncthreads();

    // ---- layer 2 (tf32): Sc(16x16) = H(16x128) @ W2f(128x16), per warp ----
    {
        wmma::fragment<wmma::matrix_a, 16, 16, 8, wmma::precision::tf32, wmma::row_major> fa2;
        wmma::fragment<wmma::matrix_b, 16, 16, 8, wmma::precision::tf32, wmma::row_major> fb2;
        wmma::fragment<wmma::accumulator, 16, 16, 8, float> fc2;
        wmma::fill_fragment(fc2, 0.f);
#pragma unroll
        for (int k = 0; k < 16; k++) {
            wmma::load_matrix_sync(fa2, H32 + 16 * w * 132 + 8 * k, 132);
            wmma::load_matrix_sync(fb2, W2f + 8 * k * 16, 16);
#pragma unroll
            for (int i = 0; i < fa2.num_elements; i++)
                fa2.x[i] = wmma::__float_to_tf32(fa2.x[i]);
#pragma unroll
            for (int i = 0; i < fb2.num_elements; i++)
                fb2.x[i] = wmma::__float_to_tf32(fb2.x[i]);
            wmma::mma_sync(fc2, fa2, fb2, fc2);
        }
        wmma::store_matrix_sync(Sc + 16 * w * 16, fc2, 16, wmma::mem_row_major);
    }
    __syncthreads();

    // ---- masked output: 448 outputs over 128 threads ----
    for (int idx = t; idx < 64 * RR; idx += 128) {
        int m = idx / RR, r = idx - m * RR;
        int bb = b0 + (m >> 3);
        int orow = bb * (GG * RR) + (m & 7) * RR;
        float v = NEGV;
        if (nodeS[m] >= 0 && mvm[orow + r] != 0)
            v = Sc[m * 16 + r] + b2s[r];
        out[orow + r] = v;
    }
}

// ---------------- launch ---------------------------------------------------
extern "C" void kernel_launch(void* const* d_in, const int* in_sizes, int n_in,
                              void* d_out, int out_size) {
    const float* nf    = (const float*)d_in[0];
    const float* gf    = (const float*)d_in[1];
    const int*   gmask = (const int*)d_in[2];
    const int*   mvm   = (const int*)d_in[3];
    const int*   batch = (const int*)d_in[4];
    const float* w1    = (const float*)d_in[5];
    const float* b1    = (const float*)d_in[6];
    const float* w2    = (const float*)d_in[7];
    const float* b2    = (const float*)d_in[8];
    float*       out   = (float*)d_out;

    cudaFuncSetAttribute(k_main, cudaFuncAttributeMaxDynamicSharedMemorySize,
                         MAIN_SMEM_BYTES);

    k_front<<<FGRID, 256>>>(gmask, batch, w1);
    k_main<<<512, 128, MAIN_SMEM_BYTES>>>(nf, gf, b1, w2, b2, mvm, out);
}